// round 3
// baseline (speedup 1.0000x reference)
#include <cuda_runtime.h>

// Shapes (fixed for this problem)
#define B_  2
#define T_  2048
#define H_  8
#define D_  64
#define M_  64
#define C_  64                 // chunk length (timesteps per block)
#define NC_ (T_ / C_)          // 32 chunks
#define RS  512                // row stride in floats between consecutive t (H*D)
#define PAD 68                 // smem row stride in floats (272B: 16B-aligned, conflict-free per 8-lane phase)
#define PAD4 (PAD / 4)         // 17 float4s per row

// Scratch: per-(b,h,chunk) partial sums of fmap(k) over the chunk. [B,H,NC,D]
__device__ float g_chunksum[B_ * H_ * NC_ * D_];

__device__ __forceinline__ float fmap(float x) {
    // elu(x) + 1 (alpha=1): x>0 -> x+1 ; x<=0 -> exp(x)
    return x > 0.0f ? x + 1.0f : __expf(x);
}
__device__ __forceinline__ float4 fmap4(float4 a) {
    return make_float4(fmap(a.x), fmap(a.y), fmap(a.z), fmap(a.w));
}
__device__ __forceinline__ float4 add4(float4 a, float4 b) {
    return make_float4(a.x + b.x, a.y + b.y, a.z + b.z, a.w + b.w);
}

// ---------------------------------------------------------------------------
// Kernel 1: per-chunk column sums of fmap(k).
// grid = B*H*NC, 256 threads. Thread (tq, dv) sums 4 timesteps for 4 d's
// (float4), then 16 threads reduce the 16 t-partials per d-group.
// ---------------------------------------------------------------------------
__global__ __launch_bounds__(256) void k_chunksum(const float* __restrict__ k) {
    __shared__ float4 red[16][16];          // [tq][dv]
    const int bc = blockIdx.x;
    const int c  = bc % NC_;
    const int h  = (bc / NC_) % H_;
    const int b  = bc / (NC_ * H_);
    const int tid = threadIdx.x;
    const int tq = tid >> 4;                // 0..15 (t-group of 4)
    const int dv = tid & 15;                // float4 index over d

    const size_t base = (((size_t)b * T_ + (size_t)c * C_) * H_ + h) * D_;

    float4 s = make_float4(0.f, 0.f, 0.f, 0.f);
    #pragma unroll
    for (int i = 0; i < 4; i++) {
        const int t = tq * 4 + i;
        float4 kv = *(const float4*)(k + base + (size_t)t * RS + dv * 4);
        s = add4(s, fmap4(kv));
    }
    red[tq][dv] = s;
    __syncthreads();

    if (tid < 16) {
        float4 acc = red[0][tid];
        #pragma unroll
        for (int t = 1; t < 16; t++) acc = add4(acc, red[t][tid]);
        *(float4*)(&g_chunksum[bc * D_ + tid * 4]) = acc;
    }
}

// ---------------------------------------------------------------------------
// Kernel 2: main. grid = B*H*NC blocks, 256 threads, fully vectorized smem.
// ---------------------------------------------------------------------------
__global__ __launch_bounds__(256) void k_main(const float* __restrict__ q,
                                              const float* __restrict__ k,
                                              const float* __restrict__ v,
                                              float* __restrict__ out) {
    extern __shared__ float sm[];
    float* kf_s   = sm;                    // C*PAD
    float* qf_s   = kf_s + C_ * PAD;       // C*PAD
    float* in_s   = qf_s + C_ * PAD;       // C*PAD
    float* segsum = in_s + C_ * PAD;       // 4*64 (float4-indexed as [4][16])
    float* carr   = segsum + 4 * 64;       // 64
    float* Sq     = carr + 64;             // 4*64
    float* Dq     = Sq + 256;              // 4*64
    float* Kq     = Dq + 256;              // 4*64
    float* Qq     = Kq + 256;              // 4*64
    float* scal   = Qq + 256;              // 64

    float4* kf4 = (float4*)kf_s;
    float4* qf4 = (float4*)qf_s;
    float4* in4 = (float4*)in_s;
    float4* ss4 = (float4*)segsum;         // [seg*16 + dv]
    float4* ca4 = (float4*)carr;           // [dv]

    const int bc  = blockIdx.x;
    const int c   = bc % NC_;
    const int h   = (bc / NC_) % H_;
    const int b   = bc / (NC_ * H_);
    const int tid = threadIdx.x;

    const size_t base = (((size_t)b * T_ + (size_t)c * C_) * H_ + h) * D_;

    // ---- Phase A: vectorized coalesced load of k,q -> fmap -> smem (STS.128) ----
    #pragma unroll
    for (int it = 0; it < 4; it++) {
        const int i  = tid + it * 256;         // 0..1023
        const int t  = i >> 4;
        const int dv = i & 15;
        const size_t g = base + (size_t)t * RS + dv * 4;
        float4 kv = *(const float4*)(k + g);
        float4 qv = *(const float4*)(q + g);
        kf4[t * PAD4 + dv] = fmap4(kv);
        qf4[t * PAD4 + dv] = fmap4(qv);
    }

    // ---- cross-chunk carry per d (threads 0..63, gmem, before sync) ----
    if (tid < D_) {
        float run = 0.0f;
        const float* cs = &g_chunksum[((b * H_ + h) * NC_) * D_ + tid];
        for (int cc = 0; cc < c; cc++) run += cs[cc * D_];
        carr[tid] = run;
    }
    __syncthreads();

    // ---- Phase B1: local inclusive time-scan, float4, 16 steps (64 threads) ----
    if (tid < 64) {
        const int dv = tid & 15, seg = tid >> 4;
        float4 run = make_float4(0.f, 0.f, 0.f, 0.f);
        #pragma unroll
        for (int i = 0; i < 16; i++) {
            const int t = seg * 16 + i;
            run = add4(run, kf4[t * PAD4 + dv]);
            in4[t * PAD4 + dv] = run;
        }
        ss4[seg * 16 + dv] = run;
    }
    __syncthreads();

    // ---- Phase B2: add carry + prior segment sums (float4) ----
    if (tid < 64) {
        const int dv = tid & 15, seg = tid >> 4;
        float4 off = ca4[dv];
        for (int s = 0; s < seg; s++) off = add4(off, ss4[s * 16 + dv]);
        #pragma unroll
        for (int i = 0; i < 16; i++) {
            const int t = seg * 16 + i;
            in4[t * PAD4 + dv] = add4(in4[t * PAD4 + dv], off);
        }
    }
    __syncthreads();

    // ---- Phase C: thread t = tid&63 handles d-quarter dq = tid>>6, LDS.128 ----
    {
        const int t = tid & 63, dq = tid >> 6;
        const int b4 = t * PAD4 + dq * 4;
        float dcum = 0.0f, S = 0.0f, den = 0.0f, qs = 0.0f;
        #pragma unroll
        for (int j = 0; j < 4; j++) {
            const float4 kf = kf4[b4 + j];
            const float4 qf = qf4[b4 + j];
            const float4 iv = in4[b4 + j];
            dcum += kf.x;  S += qf.x * dcum;
            dcum += kf.y;  S += qf.y * dcum;
            dcum += kf.z;  S += qf.z * dcum;
            dcum += kf.w;  S += qf.w * dcum;
            den += qf.x * iv.x + qf.y * iv.y + qf.z * iv.z + qf.w * iv.w;
            qs  += qf.x + qf.y + qf.z + qf.w;
        }
        Sq[dq * 64 + t] = S;
        Dq[dq * 64 + t] = den;
        Kq[dq * 64 + t] = dcum;
        Qq[dq * 64 + t] = qs;
    }
    __syncthreads();

    // ---- combine quarters: S = sum_q (S_q + ktot_{<q} * qsum_q) ----
    if (tid < C_) {
        const int t = tid;
        float kpre = 0.0f, S = 0.0f, den = 0.0f;
        #pragma unroll
        for (int qq = 0; qq < 4; qq++) {
            S    += Sq[qq * 64 + t] + kpre * Qq[qq * 64 + t];
            den  += Dq[qq * 64 + t];
            kpre += Kq[qq * 64 + t];
        }
        scal[t] = S / den;
    }
    __syncthreads();

    // ---- Phase D: vectorized coalesced output out = v * scale ----
    #pragma unroll
    for (int it = 0; it < 4; it++) {
        const int i  = tid + it * 256;
        const int t  = i >> 4;
        const int mv = i & 15;
        const size_t g = base + (size_t)t * RS + mv * 4;
        float4 vv = *(const float4*)(v + g);
        const float s = scal[t];
        vv.x *= s; vv.y *= s; vv.z *= s; vv.w *= s;
        *(float4*)(out + g) = vv;
    }
}

#define SMEM_BYTES ((3 * C_ * PAD + 4 * 64 + 64 + 4 * 256 + 64) * (int)sizeof(float))

extern "C" void kernel_launch(void* const* d_in, const int* in_sizes, int n_in,
                              void* d_out, int out_size) {
    const float* q = (const float*)d_in[0];
    const float* k = (const float*)d_in[1];
    const float* v = (const float*)d_in[2];
    float* out = (float*)d_out;

    // idempotent; SMEM_BYTES (~57KB) exceeds the 48KB default opt-in
    cudaFuncSetAttribute(k_main, cudaFuncAttributeMaxDynamicSharedMemorySize, SMEM_BYTES);

    const int nblocks = B_ * H_ * NC_;   // 512
    k_chunksum<<<nblocks, 256>>>(k);
    k_main<<<nblocks, 256, SMEM_BYTES>>>(q, k, v, out);
}

// round 4
// speedup vs baseline: 1.1555x; 1.1555x over previous
#include <cuda_runtime.h>

// Shapes (fixed for this problem)
#define B_  2
#define T_  2048
#define H_  8
#define D_  64
#define M_  64
#define C_  64                 // chunk length (timesteps per block)
#define NC_ (T_ / C_)          // 32 chunks
#define RS  512                // row stride in floats between consecutive t (H*D)
#define PAD 68                 // smem row stride in floats (272B, 16B-aligned, conflict-free)
#define PAD4 (PAD / 4)         // 17 float4s per row

// Scratch: per-(b,h,chunk) partial sums of fmap(k) over the chunk. [B,H,NC,D]
__device__ float g_chunksum[B_ * H_ * NC_ * D_];

__device__ __forceinline__ float fmap(float x) {
    // elu(x) + 1 (alpha=1): x>0 -> x+1 ; x<=0 -> exp(x)
    return x > 0.0f ? x + 1.0f : __expf(x);
}
__device__ __forceinline__ float4 fmap4(float4 a) {
    return make_float4(fmap(a.x), fmap(a.y), fmap(a.z), fmap(a.w));
}
__device__ __forceinline__ float4 add4(float4 a, float4 b) {
    return make_float4(a.x + b.x, a.y + b.y, a.z + b.z, a.w + b.w);
}

// ---------------------------------------------------------------------------
// Kernel 1: per-chunk column sums of fmap(k). grid = B*H*NC, 256 threads.
// ---------------------------------------------------------------------------
__global__ __launch_bounds__(256) void k_chunksum(const float* __restrict__ k) {
    __shared__ float4 red[16][16];          // [tq][dv]
    const int bc = blockIdx.x;
    const int c  = bc % NC_;
    const int h  = (bc / NC_) % H_;
    const int b  = bc / (NC_ * H_);
    const int tid = threadIdx.x;
    const int tq = tid >> 4;                // t-group of 4
    const int dv = tid & 15;                // float4 index over d

    const size_t base = (((size_t)b * T_ + (size_t)c * C_) * H_ + h) * D_;

    float4 s = make_float4(0.f, 0.f, 0.f, 0.f);
    #pragma unroll
    for (int i = 0; i < 4; i++) {
        const int t = tq * 4 + i;
        float4 kv = *(const float4*)(k + base + (size_t)t * RS + dv * 4);
        s = add4(s, fmap4(kv));
    }
    red[tq][dv] = s;
    __syncthreads();

    if (tid < 16) {
        float4 acc = red[0][tid];
        #pragma unroll
        for (int t = 1; t < 16; t++) acc = add4(acc, red[t][tid]);
        *(float4*)(&g_chunksum[bc * D_ + tid * 4]) = acc;
    }
}

// ---------------------------------------------------------------------------
// Kernel 2: main. grid = B*H*NC blocks, 256 threads.
// smem ~39.5KB -> 5 blocks/SM. kf tile is scanned IN PLACE (local scan, no
// carry); Phase C reconstructs kf[t] = loc[t]-loc[t-1] and folds the carry
// into den algebraically: den = qf.(loc + carr).
// ---------------------------------------------------------------------------
__global__ __launch_bounds__(256) void k_main(const float* __restrict__ q,
                                              const float* __restrict__ k,
                                              const float* __restrict__ v,
                                              float* __restrict__ out) {
    extern __shared__ float sm[];
    float* loc_s  = sm;                    // C*PAD : fmap(k) -> local time-scan (in place)
    float* qf_s   = loc_s + C_ * PAD;      // C*PAD : fmap(q)
    float* segsum = qf_s + C_ * PAD;       // 4*64
    float* carr   = segsum + 4 * 64;       // 64
    float* Sq     = carr + 64;             // 4*64
    float* Dq     = Sq + 256;              // 4*64
    float* Kq     = Dq + 256;              // 4*64
    float* Qq     = Kq + 256;              // 4*64
    float* scal   = Qq + 256;              // 64

    float4* loc4 = (float4*)loc_s;
    float4* qf4  = (float4*)qf_s;
    float4* ca4  = (float4*)carr;

    const int bc  = blockIdx.x;
    const int c   = bc % NC_;
    const int h   = (bc / NC_) % H_;
    const int b   = bc / (NC_ * H_);
    const int tid = threadIdx.x;

    const size_t base = (((size_t)b * T_ + (size_t)c * C_) * H_ + h) * D_;

    // ---- Phase A: vectorized coalesced load of k,q -> fmap -> smem (STS.128) ----
    #pragma unroll
    for (int it = 0; it < 4; it++) {
        const int i  = tid + it * 256;         // 0..1023
        const int t  = i >> 4;
        const int dv = i & 15;
        const size_t g = base + (size_t)t * RS + dv * 4;
        float4 kv = *(const float4*)(k + g);
        float4 qv = *(const float4*)(q + g);
        loc4[t * PAD4 + dv] = fmap4(kv);
        qf4[t * PAD4 + dv]  = fmap4(qv);
    }

    // ---- cross-chunk carry per d (threads 0..63, independent LDGs) ----
    if (tid < D_) {
        float run = 0.0f;
        const float* cs = &g_chunksum[((b * H_ + h) * NC_) * D_ + tid];
        #pragma unroll 4
        for (int cc = 0; cc < c; cc++) run += cs[cc * D_];
        carr[tid] = run;
    }
    __syncthreads();

    // ---- Phase B1: local inclusive time-scan IN PLACE (256 threads: d x seg) ----
    {
        const int d = tid & 63, seg = tid >> 6;
        float run = 0.0f;
        #pragma unroll
        for (int i = 0; i < 16; i++) {
            const int t = seg * 16 + i;
            run += loc_s[t * PAD + d];
            loc_s[t * PAD + d] = run;
        }
        segsum[seg * 64 + d] = run;
    }
    __syncthreads();

    // ---- Phase B2: add prior-segment offsets (seg 0 skips) ----
    {
        const int d = tid & 63, seg = tid >> 6;
        if (seg > 0) {
            float off = segsum[d];
            for (int s = 1; s < seg; s++) off += segsum[s * 64 + d];
            #pragma unroll
            for (int i = 0; i < 16; i++) {
                const int t = seg * 16 + i;
                loc_s[t * PAD + d] += off;
            }
        }
    }
    __syncthreads();

    // ---- Phase C: thread t = tid&63 handles d-quarter dq = tid>>6 (LDS.128) ----
    {
        const int t = tid & 63, dq = tid >> 6;
        const int b4 = t * PAD4 + dq * 4;
        float dcum = 0.0f, S = 0.0f, den = 0.0f, qs = 0.0f;
        #pragma unroll
        for (int j = 0; j < 4; j++) {
            const float4 lv = loc4[b4 + j];
            float4 pv = make_float4(0.f, 0.f, 0.f, 0.f);
            if (t > 0) pv = loc4[b4 - PAD4 + j];
            const float4 qf = qf4[b4 + j];
            const float4 cv = ca4[dq * 4 + j];     // warp-uniform -> broadcast

            den += qf.x * (lv.x + cv.x) + qf.y * (lv.y + cv.y)
                 + qf.z * (lv.z + cv.z) + qf.w * (lv.w + cv.w);

            dcum += lv.x - pv.x;  S += qf.x * dcum;
            dcum += lv.y - pv.y;  S += qf.y * dcum;
            dcum += lv.z - pv.z;  S += qf.z * dcum;
            dcum += lv.w - pv.w;  S += qf.w * dcum;
            qs   += qf.x + qf.y + qf.z + qf.w;
        }
        Sq[dq * 64 + t] = S;
        Dq[dq * 64 + t] = den;
        Kq[dq * 64 + t] = dcum;
        Qq[dq * 64 + t] = qs;
    }
    __syncthreads();

    // ---- combine quarters: S = sum_q (S_q + ktot_{<q} * qsum_q) ----
    if (tid < C_) {
        const int t = tid;
        float kpre = 0.0f, S = 0.0f, den = 0.0f;
        #pragma unroll
        for (int qq = 0; qq < 4; qq++) {
            S    += Sq[qq * 64 + t] + kpre * Qq[qq * 64 + t];
            den  += Dq[qq * 64 + t];
            kpre += Kq[qq * 64 + t];
        }
        scal[t] = S / den;
    }
    __syncthreads();

    // ---- Phase D: vectorized coalesced output out = v * scale ----
    #pragma unroll
    for (int it = 0; it < 4; it++) {
        const int i  = tid + it * 256;
        const int t  = i >> 4;
        const int mv = i & 15;
        const size_t g = base + (size_t)t * RS + mv * 4;
        float4 vv = *(const float4*)(v + g);
        const float s = scal[t];
        vv.x *= s; vv.y *= s; vv.z *= s; vv.w *= s;
        *(float4*)(out + g) = vv;
    }
}

#define SMEM_BYTES ((2 * C_ * PAD + 4 * 64 + 64 + 4 * 256 + 64) * (int)sizeof(float))

extern "C" void kernel_launch(void* const* d_in, const int* in_sizes, int n_in,
                              void* d_out, int out_size) {
    const float* q = (const float*)d_in[0];
    const float* k = (const float*)d_in[1];
    const float* v = (const float*)d_in[2];
    float* out = (float*)d_out;

    cudaFuncSetAttribute(k_main, cudaFuncAttributeMaxDynamicSharedMemorySize, SMEM_BYTES);

    const int nblocks = B_ * H_ * NC_;   // 512
    k_chunksum<<<nblocks, 256>>>(k);
    k_main<<<nblocks, 256, SMEM_BYTES>>>(q, k, v, out);
}